// round 15
// baseline (speedup 1.0000x reference)
#include <cuda_runtime.h>
#include <cuda_fp16.h>
#include <cstdint>
#include <math.h>

#define HEADS   8
#define DH      64
#define NSEQ    2048
#define BATCH   4
#define DMODEL  512
#define ROWS    (BATCH*NSEQ)    // 8192
#define BHN     (BATCH*HEADS)   // 32

// ---------------- scratch (device globals; no allocations) ----------------
__device__ __half g_Xh[(size_t)ROWS*DMODEL];
__device__ __half g_Wqh[(size_t)DMODEL*3*DMODEL];
__device__ __half g_Qh[(size_t)BHN*NSEQ*DH];
__device__ __half g_Kh[(size_t)BHN*NSEQ*DH];
__device__ __half g_Vh[(size_t)BHN*NSEQ*DH];
__device__ float  g_O[(size_t)ROWS*DMODEL];
__device__ float  g_Y[(size_t)ROWS*DMODEL];
__device__ float  g_inv[(size_t)BHN*NSEQ];

#define DECSTEP128 0.0773047404f   // exp(-128/50)
#define DECSTEP64  0.2780373005f   // exp(-64/50)
#define DEC1       0.9801986694f   // exp(-1/50)

// ================= warp-level tensor core helpers (sm_80+ ISA) =============
__device__ __forceinline__ uint32_t smem_u32(const void* p) {
    uint32_t a;
    asm("{ .reg .u64 t; cvta.to.shared.u64 t, %1; cvt.u32.u64 %0, t; }"
        : "=r"(a) : "l"(p));
    return a;
}
__device__ __forceinline__ void ldsm4(uint32_t* r, uint32_t a) {
    asm volatile("ldmatrix.sync.aligned.m8n8.x4.shared.b16 {%0,%1,%2,%3}, [%4];"
        : "=r"(r[0]), "=r"(r[1]), "=r"(r[2]), "=r"(r[3]) : "r"(a));
}
__device__ __forceinline__ void ldsm2(uint32_t* r, uint32_t a) {
    asm volatile("ldmatrix.sync.aligned.m8n8.x2.shared.b16 {%0,%1}, [%2];"
        : "=r"(r[0]), "=r"(r[1]) : "r"(a));
}
__device__ __forceinline__ void ldsm2t(uint32_t* r, uint32_t a) {
    asm volatile("ldmatrix.sync.aligned.m8n8.x2.trans.shared.b16 {%0,%1}, [%2];"
        : "=r"(r[0]), "=r"(r[1]) : "r"(a));
}
__device__ __forceinline__ void mma16816(float* d, const uint32_t* a, const uint32_t* b) {
    asm volatile("mma.sync.aligned.m16n8k16.row.col.f32.f16.f16.f32 "
        "{%0,%1,%2,%3}, {%4,%5,%6,%7}, {%8,%9}, {%0,%1,%2,%3};"
        : "+f"(d[0]), "+f"(d[1]), "+f"(d[2]), "+f"(d[3])
        : "r"(a[0]), "r"(a[1]), "r"(a[2]), "r"(a[3]), "r"(b[0]), "r"(b[1]));
}
__device__ __forceinline__ void cp16(uint32_t dst, const void* src) {
    asm volatile("cp.async.cg.shared.global [%0], [%1], 16;" :: "r"(dst), "l"(src));
}
#define CP_COMMIT() asm volatile("cp.async.commit_group;" ::: "memory")
#define CP_WAIT0()  asm volatile("cp.async.wait_group 0;" ::: "memory")
// streaming fp32x2 store (evict-first; attn is write-once)
__device__ __forceinline__ void stcs2(float* p, float x, float y) {
    asm volatile("st.global.cs.v2.f32 [%0], {%1, %2};" :: "l"(p), "f"(x), "f"(y) : "memory");
}

__device__ __forceinline__ void split_pack_h(float4 f, uint2& uh, uint2& ul) {
    __half h0 = __float2half_rn(f.x), h1 = __float2half_rn(f.y),
           h2 = __float2half_rn(f.z), h3 = __float2half_rn(f.w);
    __half l0 = __float2half_rn(f.x - __half2float(h0));
    __half l1 = __float2half_rn(f.y - __half2float(h1));
    __half l2 = __float2half_rn(f.z - __half2float(h2));
    __half l3 = __float2half_rn(f.w - __half2float(h3));
    uh.x = (uint32_t)__half_as_ushort(h0) | ((uint32_t)__half_as_ushort(h1) << 16);
    uh.y = (uint32_t)__half_as_ushort(h2) | ((uint32_t)__half_as_ushort(h3) << 16);
    ul.x = (uint32_t)__half_as_ushort(l0) | ((uint32_t)__half_as_ushort(l1) << 16);
    ul.y = (uint32_t)__half_as_ushort(l2) | ((uint32_t)__half_as_ushort(l3) << 16);
}
__device__ __forceinline__ uint2 pack_hi4(float4 f) {
    uint2 u;
    u.x = (uint32_t)__half_as_ushort(__float2half_rn(f.x)) |
          ((uint32_t)__half_as_ushort(__float2half_rn(f.y)) << 16);
    u.y = (uint32_t)__half_as_ushort(__float2half_rn(f.z)) |
          ((uint32_t)__half_as_ushort(__float2half_rn(f.w)) << 16);
    return u;
}
__device__ __forceinline__ uint32_t pack2hi(float x, float y) {
    return (uint32_t)__half_as_ushort(__float2half_rn(x)) |
           ((uint32_t)__half_as_ushort(__float2half_rn(y)) << 16);
}

// ============ one-time fp32 -> fp16 conversion of x and w_qkv ==============
#define X4 ((size_t)ROWS*DMODEL/4)
#define W4 ((size_t)DMODEL*3*DMODEL/4)

__global__ void __launch_bounds__(256)
cvt16(const float* __restrict__ x, const float* __restrict__ w)
{
    const size_t i4 = (size_t)blockIdx.x*256 + threadIdx.x;
    if (i4 < X4) {
        ((uint2*)g_Xh)[i4] = pack_hi4(((const float4*)x)[i4]);
    } else if (i4 < X4 + W4) {
        const size_t j = i4 - X4;
        ((uint2*)g_Wqh)[j] = pack_hi4(((const float4*)w)[j]);
    }
}

// ======== QKV projection: 1-product fp16, cp.async staging =================
#define GQ_AH   0
#define GQ_BH   18432
#define GQ_SMEM 35840

__global__ void __launch_bounds__(256, 2)
gemm_qkv()
{
    extern __shared__ char sm[];
    const uint32_t smb = smem_u32(sm);

    const int bm = blockIdx.y * 128;
    const int bn = blockIdx.x * 128;
    const int tid = threadIdx.x;
    const int wid = tid >> 5, lane = tid & 31;

    const int wq = (wid & 3)*32, nw = (wid >> 2)*64;
    const int l15 = lane & 15;
    const int lq = lane >> 4;
    const int g = lane >> 2, cq = (lane & 3)*2;

    float acc[2][8][4];
    #pragma unroll
    for (int mf = 0; mf < 2; mf++)
        #pragma unroll
        for (int nf = 0; nf < 8; nf++)
            #pragma unroll
            for (int e = 0; e < 4; e++) acc[mf][nf][e] = 0.f;

    for (int ks0 = 0; ks0 < 8; ++ks0) {
        const int k0 = ks0*64;
        __syncthreads();
        #pragma unroll
        for (int i = 0; i < 4; i++) {
            const int f = i*256 + tid;
            const int row = f >> 3, c8 = f & 7;
            cp16(smb + GQ_AH + row*144 + c8*16,
                 g_Xh + (size_t)(bm + row)*512 + k0 + c8*8);
        }
        #pragma unroll
        for (int i = 0; i < 4; i++) {
            const int f = i*256 + tid;
            const int row = f >> 4, c16 = f & 15;
            cp16(smb + GQ_BH + row*272 + c16*16,
                 g_Wqh + (size_t)(k0 + row)*(3*DMODEL) + bn + c16*8);
        }
        CP_COMMIT();
        CP_WAIT0();
        __syncthreads();

        #pragma unroll
        for (int ks = 0; ks < 4; ks++) {
            uint32_t ah[2][4];
            #pragma unroll
            for (int mf = 0; mf < 2; mf++)
                ldsm4(ah[mf], smb + GQ_AH + (wq + mf*16 + l15)*144 + (ks*16 + lq*8)*2);
            #pragma unroll
            for (int nf = 0; nf < 8; nf++) {
                uint32_t bhf[2];
                ldsm2t(bhf, smb + GQ_BH + (ks*16 + l15)*272 + (nw + nf*8)*2);
                #pragma unroll
                for (int mf = 0; mf < 2; mf++)
                    mma16816(acc[mf][nf], ah[mf], bhf);
            }
        }
    }

    const int which = bn >> 9;
    __half* dst = (which == 0) ? g_Qh : (which == 1) ? g_Kh : g_Vh;
    const int cbase = bn & 511;
    #pragma unroll
    for (int mf = 0; mf < 2; mf++) {
        const int r = bm + wq + mf*16 + g;
        const int bidx = r >> 11, nidx = r & (NSEQ-1);
        #pragma unroll
        for (int nf = 0; nf < 8; nf++) {
            const int cb = cbase + nw + nf*8 + cq;
            const int h = cb >> 6, dd = cb & 63;
            __half* hp = dst + (((size_t)bidx*HEADS + h)*NSEQ + nidx)*DH + dd;
            *(uint32_t*)(hp)        = pack2hi(acc[mf][nf][0], acc[mf][nf][1]);
            *(uint32_t*)(hp + 8*DH) = pack2hi(acc[mf][nf][2], acc[mf][nf][3]);
        }
    }
}

// ===== attn pass 1: 16 q-rows/warp, no cross-warp reduce, 3 CTAs/SM ========
// smem: Q 0..18432 | stage 2x(K 9216 + V 9216) = 18432..55296
#define AF_QH    0
#define AF_ST    18432
#define AF_BUFSZ 18432
#define AF_SMEM  55296

__global__ void __launch_bounds__(256, 3)
attn_pass1()
{
    extern __shared__ char sm[];
    const uint32_t smb = smem_u32(sm);
    const int tid = threadIdx.x;
    const int wid = tid >> 5, lane = tid & 31;
    const int q0 = blockIdx.x * 128;
    const int bh = blockIdx.y;

    const int mw = wid*16;                   // warp owns q rows [mw, mw+16)
    const int l15 = lane & 15, l7 = lane & 7;
    const int lh = (lane >> 3) & 1, lq = lane >> 4;
    const int g = lane >> 2, cq = (lane & 3)*2;

    const __half* Qb = g_Qh + ((size_t)bh*NSEQ + q0)*DH;
    const __half* Kb = g_Kh + (size_t)bh*NSEQ*DH;
    const __half* Vb = g_Vh + (size_t)bh*NSEQ*DH;

    // stage Q + slab 0 (one cp.async group)
    #pragma unroll
    for (int i = 0; i < 4; i++) {
        const int f = i*256 + tid;
        const int row = f >> 3, c8 = f & 7;
        cp16(smb + AF_QH + row*144 + c8*16, Qb + (size_t)row*DH + c8*8);
    }
    #pragma unroll
    for (int i = 0; i < 2; i++) {
        const int f = i*256 + tid;
        const int row = f >> 3, c8 = f & 7;
        const int boff = row*144 + c8*16;
        cp16(smb + AF_ST + boff,        Kb + (size_t)row*DH + c8*8);
        cp16(smb + AF_ST + 9216 + boff, Vb + (size_t)row*DH + c8*8);
    }
    CP_COMMIT();

    float acc_o[8][4];
    #pragma unroll
    for (int nf = 0; nf < 8; nf++)
        #pragma unroll
        for (int e = 0; e < 4; e++) acc_o[nf][e] = 0.f;
    float psum0 = 0.f, psum1 = 0.f;

    float decv[8];
    #pragma unroll
    for (int nf = 0; nf < 8; nf++)
        decv[nf] = __expf((float)(nf*8 + cq) * -0.02f);

    for (int kt = 0; kt < 32; ++kt) {
        CP_WAIT0();
        __syncthreads();
        const uint32_t bK = smb + AF_ST + (kt & 1)*AF_BUFSZ;
        const uint32_t bV = bK + 9216;

        if (kt < 31) {
            const int kb1 = (kt + 1)*64;
            const uint32_t nK = smb + AF_ST + ((kt + 1) & 1)*AF_BUFSZ;
            #pragma unroll
            for (int i = 0; i < 2; i++) {
                const int f = i*256 + tid;
                const int row = f >> 3, c8 = f & 7;
                const int boff = row*144 + c8*16;
                cp16(nK + boff,        Kb + (size_t)(kb1 + row)*DH + c8*8);
                cp16(nK + 9216 + boff, Vb + (size_t)(kb1 + row)*DH + c8*8);
            }
            CP_COMMIT();
        }

        // S = Q(16q x 64d) K^T(64k x 64d)
        float acc_s[8][4];
        #pragma unroll
        for (int nf = 0; nf < 8; nf++)
            #pragma unroll
            for (int e = 0; e < 4; e++) acc_s[nf][e] = 0.f;
        #pragma unroll
        for (int ks = 0; ks < 4; ks++) {
            uint32_t ah[4];
            ldsm4(ah, smb + AF_QH + (mw + l15)*144 + (ks*16 + lq*8)*2);
            #pragma unroll
            for (int nf = 0; nf < 8; nf++) {
                uint32_t bhf[2];
                ldsm2(bhf, bK + (nf*8 + l7)*144 + (ks*16 + lh*8)*2);
                mma16816(acc_s[nf], ah, bhf);
            }
        }

        // exp + rowsum + hi-only E fragments
        uint32_t eh[8][2];
        #pragma unroll
        for (int nf = 0; nf < 8; nf++) {
            const float dec0 = decv[nf];
            const float dec1 = dec0 * DEC1;
            decv[nf] = dec0 * DECSTEP64;
            const float e0 = __expf(fmaf(acc_s[nf][0], 0.125f, dec0));
            const float e1 = __expf(fmaf(acc_s[nf][1], 0.125f, dec1));
            const float e2 = __expf(fmaf(acc_s[nf][2], 0.125f, dec0));
            const float e3 = __expf(fmaf(acc_s[nf][3], 0.125f, dec1));
            psum0 += e0 + e1;
            psum1 += e2 + e3;
            eh[nf][0] = pack2hi(e0, e1);
            eh[nf][1] = pack2hi(e2, e3);
        }

        // PV: O(16q x 64d) += E(16q x 64k) V(64k x 64d)
        #pragma unroll
        for (int ks2 = 0; ks2 < 4; ks2++) {
            uint32_t pah[4];
            pah[0] = eh[2*ks2][0];
            pah[1] = eh[2*ks2][1];
            pah[2] = eh[2*ks2+1][0];
            pah[3] = eh[2*ks2+1][1];
            #pragma unroll
            for (int nf = 0; nf < 8; nf++) {
                uint32_t bhf[2];
                ldsm2t(bhf, bV + (ks2*16 + l15)*144 + (nf*8)*2);
                mma16816(acc_o[nf], pah, bhf);
            }
        }
    }

    // rowsums complete within warp: reduce over the 4 lanes sharing a row
    psum0 += __shfl_xor_sync(0xffffffffu, psum0, 1);
    psum0 += __shfl_xor_sync(0xffffffffu, psum0, 2);
    psum1 += __shfl_xor_sync(0xffffffffu, psum1, 1);
    psum1 += __shfl_xor_sync(0xffffffffu, psum1, 2);
    const float inv0 = 1.0f / psum0;
    const float inv1 = 1.0f / psum1;
    if ((lane & 3) == 0) {
        g_inv[(size_t)bh*NSEQ + q0 + mw + g]     = inv0;
        g_inv[(size_t)bh*NSEQ + q0 + mw + 8 + g] = inv1;
    }

    // scale + write O directly (warp owns its rows)
    const int b = bh >> 3, h = bh & 7;
    const int r0 = q0 + mw + g;
    #pragma unroll
    for (int nf = 0; nf < 8; nf++) {
        float* op = g_O + (size_t)(b*NSEQ + r0)*DMODEL + h*DH + nf*8 + cq;
        *(float2*)(op)            = make_float2(acc_o[nf][0]*inv0, acc_o[nf][1]*inv0);
        *(float2*)(op + 8*DMODEL) = make_float2(acc_o[nf][2]*inv1, acc_o[nf][3]*inv1);
    }
}

// ===== merged kernel: blocks 0..255 = unify GEMM; 256..767 = attn pass2 ====
#define PU_SMEM 55808

__global__ void __launch_bounds__(256, 2)
pass2_unify(float* __restrict__ attn, const float* __restrict__ B,
            const float* __restrict__ bias)
{
    extern __shared__ char sm[];
    const uint32_t smb = smem_u32(sm);
    const int tid = threadIdx.x;
    const int wid = tid >> 5, lane = tid & 31;
    const int l15 = lane & 15, l7 = lane & 7;
    const int lh = (lane >> 3) & 1, lq = lane >> 4;
    const int g = lane >> 2, cq = (lane & 3)*2;

    if (blockIdx.x < 256) {
        // ---------------- unify GEMM role (A hi, B hi+lo) ----------------
        const int bn = (blockIdx.x & 3)*128;
        const int bm = (blockIdx.x >> 2)*128;
        const int wq = (wid & 3)*32, nw = (wid >> 2)*64;

        float acc[2][8][4];
        #pragma unroll
        for (int mf = 0; mf < 2; mf++)
            #pragma unroll
            for (int nf = 0; nf < 8; nf++)
                #pragma unroll
                for (int e = 0; e < 4; e++) acc[mf][nf][e] = 0.f;

        for (int ks0 = 0; ks0 < 8; ++ks0) {
            const int k0 = ks0*64;
            __syncthreads();
            #pragma unroll
            for (int i = 0; i < 8; i++) {
                const int f = i*256 + tid;
                float4 a = *(const float4*)(g_O + (size_t)(bm + (f >> 4))*512 + k0 + (f & 15)*4);
                *(uint2*)(sm + (f >> 4)*144 + (f & 15)*8) = pack_hi4(a);
            }
            #pragma unroll
            for (int i = 0; i < 8; i++) {
                const int f = i*256 + tid;
                float4 b = *(const float4*)(B + (size_t)(k0 + (f >> 5))*DMODEL + bn + (f & 31)*4);
                uint2 uh, ul;
                split_pack_h(b, uh, ul);
                const int boff = (f >> 5)*272 + (f & 31)*8;
                *(uint2*)(sm + 18432 + boff) = uh;
                *(uint2*)(sm + 35840 + boff) = ul;
            }
            __syncthreads();

            #pragma unroll
            for (int ks = 0; ks < 4; ks++) {
                uint32_t ah[2][4];
                #pragma unroll
                for (int mf = 0; mf < 2; mf++)
                    ldsm4(ah[mf], smb + (wq + mf*16 + l15)*144 + (ks*16 + lq*8)*2);
                #pragma unroll
                for (int nf = 0; nf < 8; nf++) {
                    const uint32_t bo = (ks*16 + l15)*272 + (nw + nf*8)*2;
                    uint32_t bhf[2], blf[2];
                    ldsm2t(bhf, smb + 18432 + bo);
                    ldsm2t(blf, smb + 35840 + bo);
                    #pragma unroll
                    for (int mf = 0; mf < 2; mf++) {
                        mma16816(acc[mf][nf], ah[mf], bhf);
                        mma16816(acc[mf][nf], ah[mf], blf);
                    }
                }
            }
        }

        #pragma unroll
        for (int mf = 0; mf < 2; mf++) {
            const int r = bm + wq + mf*16 + g;
            #pragma unroll
            for (int nf = 0; nf < 8; nf++) {
                const int col = bn + nw + nf*8 + cq;
                const float b0 = bias[col], b1 = bias[col + 1];
                float* yr = g_Y + (size_t)r*DMODEL + col;
                *(float2*)(yr)            = make_float2(acc[mf][nf][0] + b0,
                                                        acc[mf][nf][1] + b1);
                *(float2*)(yr + 8*DMODEL) = make_float2(acc[mf][nf][2] + b0,
                                                        acc[mf][nf][3] + b1);
            }
        }
    } else {
        // ---------------- attn pass-2 role (cp.async + streaming stores) --
        const int t = blockIdx.x - 256;
        const int q0 = (t & 15)*128;
        const int bh = t >> 4;
        const int mw = (wid & 3)*32, nw = (wid >> 2)*64;
        float* invs = (float*)(sm + 55296);

        const __half* Qb = g_Qh + ((size_t)bh*NSEQ + q0)*DH;
        const __half* Kb = g_Kh + (size_t)bh*NSEQ*DH;

        #pragma unroll
        for (int i = 0; i < 4; i++) {
            const int f = i*256 + tid;
            const int row = f >> 3, c8 = f & 7;
            cp16(smb + row*144 + c8*16, Qb + (size_t)row*DH + c8*8);
        }
        #pragma unroll
        for (int i = 0; i < 4; i++) {
            const int f = i*256 + tid;
            const int row = f >> 3, c8 = f & 7;
            cp16(smb + 18432 + row*144 + c8*16, Kb + (size_t)row*DH + c8*8);
        }
        CP_COMMIT();
        if (tid < 128) invs[tid] = g_inv[(size_t)bh*NSEQ + q0 + tid];

        float decv[8];
        #pragma unroll
        for (int nf = 0; nf < 8; nf++)
            decv[nf] = __expf((float)(nw + nf*8 + cq) * -0.02f);

        for (int kt = 0; kt < 16; ++kt) {
            CP_WAIT0();
            __syncthreads();
            const uint32_t bK = smb + 18432 + (kt & 1)*18432;

            if (kt < 15) {
                const int kb1 = (kt + 1)*128;
                const uint32_t nK = smb + 18432 + ((kt + 1) & 1)*18432;
                #pragma unroll
                for (int i = 0; i < 4; i++) {
                    const int f = i*256 + tid;
                    const int row = f >> 3, c8 = f & 7;
                    cp16(nK + row*144 + c8*16, Kb + (size_t)(kb1 + row)*DH + c8*8);
                }
                CP_COMMIT();
            }

            const int kb = kt*128;
            float acc_s[2][8][4];
            #pragma unroll
            for (int mf = 0; mf < 2; mf++)
                #pragma unroll
                for (int nf = 0; nf < 8; nf++)
                    #pragma unroll
                    for (int e = 0; e < 4; e++) acc_s[mf][nf][e] = 0.f;
            #pragma unroll
            for (int ks = 0; ks < 4; ks++) {
                uint32_t ah[2][4];
                #pragma unroll
                for (int mf = 0; mf < 2; mf++)
                    ldsm4(ah[mf], smb + (mw + mf*16 + l15)*144 + (ks*16 + lq*8)*2);
                #pragma unroll
                for (int nf = 0; nf < 8; nf++) {
                    uint32_t bhf[2];
                    ldsm2(bhf, bK + (nw + nf*8 + l7)*144 + (ks*16 + lh*8)*2);
                    #pragma unroll
                    for (int mf = 0; mf < 2; mf++)
                        mma16816(acc_s[mf][nf], ah[mf], bhf);
                }
            }

            #pragma unroll
            for (int nf = 0; nf < 8; nf++) {
                const float dec0 = decv[nf];
                const float dec1 = dec0 * DEC1;
                decv[nf] = dec0 * DECSTEP128;
                const int c = nw + nf*8 + cq;
                #pragma unroll
                for (int mf = 0; mf < 2; mf++) {
                    const float inv0 = invs[mw + mf*16 + g];
                    const float inv1 = invs[mw + mf*16 + 8 + g];
                    const int r0 = q0 + mw + mf*16 + g;
                    const float e0 = __expf(fmaf(acc_s[mf][nf][0], 0.125f, dec0)) * inv0;
                    const float e1 = __expf(fmaf(acc_s[mf][nf][1], 0.125f, dec1)) * inv0;
                    const float e2 = __expf(fmaf(acc_s[mf][nf][2], 0.125f, dec0)) * inv1;
                    const float e3 = __expf(fmaf(acc_s[mf][nf][3], 0.125f, dec1)) * inv1;
                    float* p = attn + ((size_t)bh*NSEQ + r0)*NSEQ + kb + c;
                    stcs2(p, e0, e1);
                    stcs2(p + 8*NSEQ, e2, e3);
                }
            }
        }
    }
}

// ---------------- LayerNorm (unchanged; clock canary ~13 µs) ---------------
__global__ void __launch_bounds__(256)
ln_kernel(const float* __restrict__ gamma, const float* __restrict__ beta,
          float* __restrict__ out)
{
    const int r = blockIdx.x, tid = threadIdx.x;
    const float* y = g_Y + (size_t)r*DMODEL;
    const float a = y[tid], b = y[tid + 256];
    float s  = a + b;
    float sq = a*a + b*b;
    #pragma unroll
    for (int off = 16; off; off >>= 1) {
        s  += __shfl_xor_sync(0xffffffffu, s,  off);
        sq += __shfl_xor_sync(0xffffffffu, sq, off);
    }
    __shared__ float ws[8], wq[8];
    __shared__ float mean_s, inv_s;
    if ((tid & 31) == 0) { ws[tid >> 5] = s; wq[tid >> 5] = sq; }
    __syncthreads();
    if (tid == 0) {
        float S = 0.f, Q = 0.f;
        #pragma unroll
        for (int i = 0; i < 8; i++) { S += ws[i]; Q += wq[i]; }
        const float mean = S * (1.0f/512.0f);
        const float var  = Q * (1.0f/512.0f) - mean*mean;
        mean_s = mean;
        inv_s  = rsqrtf(var + 1e-5f);
    }
    __syncthreads();
    out[(size_t)r*DMODEL + tid]       = (a - mean_s)*inv_s*gamma[tid]       + beta[tid];
    out[(size_t)r*DMODEL + tid + 256] = (b - mean_s)*inv_s*gamma[tid + 256] + beta[tid + 256];
}

// ---------------- launch ---------------------------------------------------
extern "C" void kernel_launch(void* const* d_in, const int* in_sizes, int n_in,
                              void* d_out, int out_size)
{
    const float* x        = (const float*)d_in[0];
    const float* w_qkv    = (const float*)d_in[1];
    const float* w_unify  = (const float*)d_in[2];
    const float* b_unify  = (const float*)d_in[3];
    const float* ln_gamma = (const float*)d_in[4];
    const float* ln_beta  = (const float*)d_in[5];

    float* out_ln   = (float*)d_out;
    float* out_attn = out_ln + (size_t)ROWS*DMODEL;

    cudaFuncSetAttribute(gemm_qkv,    cudaFuncAttributeMaxDynamicSharedMemorySize, GQ_SMEM);
    cudaFuncSetAttribute(attn_pass1,  cudaFuncAttributeMaxDynamicSharedMemorySize, AF_SMEM);
    cudaFuncSetAttribute(pass2_unify, cudaFuncAttributeMaxDynamicSharedMemorySize, PU_SMEM);

    // 0) one-time fp16 conversion of x and w_qkv
    cvt16<<<(unsigned)((X4 + W4 + 255)/256), 256>>>(x, w_qkv);
    // 1) QKV projection -> fp16 [bh][n][dh]
    gemm_qkv<<<dim3(12, 64), 256, GQ_SMEM>>>();
    // 2) attention pass 1: rowsums (g_inv) + O (g_O), 3 CTAs/SM
    attn_pass1<<<dim3(16, 32), 256, AF_SMEM>>>();
    // 3) merged: unify GEMM (blocks 0-255) + attn pass 2 (blocks 256-767)
    pass2_unify<<<768, 256, PU_SMEM>>>(out_attn, w_unify, b_unify);
    // 4) LayerNorm -> first output
    ln_kernel<<<ROWS, 256>>>(ln_gamma, ln_beta, out_ln);
}

// round 16
// speedup vs baseline: 1.0473x; 1.0473x over previous
#include <cuda_runtime.h>
#include <cuda_fp16.h>
#include <cstdint>
#include <math.h>

#define HEADS   8
#define DH      64
#define NSEQ    2048
#define BATCH   4
#define DMODEL  512
#define ROWS    (BATCH*NSEQ)    // 8192
#define BHN     (BATCH*HEADS)   // 32

// ---------------- scratch (device globals; no allocations) ----------------
__device__ __half g_Xh[(size_t)ROWS*DMODEL];
__device__ __half g_Wqh[(size_t)DMODEL*3*DMODEL];
__device__ __half g_Qh[(size_t)BHN*NSEQ*DH];
__device__ __half g_Kh[(size_t)BHN*NSEQ*DH];
__device__ __half g_Vh[(size_t)BHN*NSEQ*DH];
__device__ float  g_O[(size_t)ROWS*DMODEL];
__device__ float  g_Y[(size_t)ROWS*DMODEL];
__device__ float  g_inv[(size_t)BHN*NSEQ];

#define DECSTEP128 0.0773047404f   // exp(-128/50)
#define DECSTEP64  0.2780373005f   // exp(-64/50)

// ================= warp-level tensor core helpers (sm_80+ ISA) =============
__device__ __forceinline__ uint32_t smem_u32(const void* p) {
    uint32_t a;
    asm("{ .reg .u64 t; cvta.to.shared.u64 t, %1; cvt.u32.u64 %0, t; }"
        : "=r"(a) : "l"(p));
    return a;
}
__device__ __forceinline__ void ldsm4(uint32_t* r, uint32_t a) {
    asm volatile("ldmatrix.sync.aligned.m8n8.x4.shared.b16 {%0,%1,%2,%3}, [%4];"
        : "=r"(r[0]), "=r"(r[1]), "=r"(r[2]), "=r"(r[3]) : "r"(a));
}
__device__ __forceinline__ void ldsm2(uint32_t* r, uint32_t a) {
    asm volatile("ldmatrix.sync.aligned.m8n8.x2.shared.b16 {%0,%1}, [%2];"
        : "=r"(r[0]), "=r"(r[1]) : "r"(a));
}
__device__ __forceinline__ void ldsm2t(uint32_t* r, uint32_t a) {
    asm volatile("ldmatrix.sync.aligned.m8n8.x2.trans.shared.b16 {%0,%1}, [%2];"
        : "=r"(r[0]), "=r"(r[1]) : "r"(a));
}
__device__ __forceinline__ void mma16816(float* d, const uint32_t* a, const uint32_t* b) {
    asm volatile("mma.sync.aligned.m16n8k16.row.col.f32.f16.f16.f32 "
        "{%0,%1,%2,%3}, {%4,%5,%6,%7}, {%8,%9}, {%0,%1,%2,%3};"
        : "+f"(d[0]), "+f"(d[1]), "+f"(d[2]), "+f"(d[3])
        : "r"(a[0]), "r"(a[1]), "r"(a[2]), "r"(a[3]), "r"(b[0]), "r"(b[1]));
}
__device__ __forceinline__ void cp16(uint32_t dst, const void* src) {
    asm volatile("cp.async.cg.shared.global [%0], [%1], 16;" :: "r"(dst), "l"(src));
}
#define CP_COMMIT() asm volatile("cp.async.commit_group;" ::: "memory")
#define CP_WAIT0()  asm volatile("cp.async.wait_group 0;" ::: "memory")

__device__ __forceinline__ uint2 pack_hi4(float4 f) {
    uint2 u;
    u.x = (uint32_t)__half_as_ushort(__float2half_rn(f.x)) |
          ((uint32_t)__half_as_ushort(__float2half_rn(f.y)) << 16);
    u.y = (uint32_t)__half_as_ushort(__float2half_rn(f.z)) |
          ((uint32_t)__half_as_ushort(__float2half_rn(f.w)) << 16);
    return u;
}
__device__ __forceinline__ uint32_t pack2hi(float x, float y) {
    return (uint32_t)__half_as_ushort(__float2half_rn(x)) |
           ((uint32_t)__half_as_ushort(__float2half_rn(y)) << 16);
}

// ============ one-time fp32 -> fp16 conversion of x and w_qkv ==============
#define X4 ((size_t)ROWS*DMODEL/4)
#define W4 ((size_t)DMODEL*3*DMODEL/4)

__global__ void __launch_bounds__(256)
cvt16(const float* __restrict__ x, const float* __restrict__ w)
{
    const size_t i4 = (size_t)blockIdx.x*256 + threadIdx.x;
    if (i4 < X4) {
        ((uint2*)g_Xh)[i4] = pack_hi4(((const float4*)x)[i4]);
    } else if (i4 < X4 + W4) {
        const size_t j = i4 - X4;
        ((uint2*)g_Wqh)[j] = pack_hi4(((const float4*)w)[j]);
    }
}

// ======== QKV projection: 1-product fp16, cp.async staging =================
#define GQ_AH   0
#define GQ_BH   18432
#define GQ_SMEM 35840

__global__ void __launch_bounds__(256, 2)
gemm_qkv()
{
    extern __shared__ char sm[];
    const uint32_t smb = smem_u32(sm);

    const int bm = blockIdx.y * 128;
    const int bn = blockIdx.x * 128;
    const int tid = threadIdx.x;
    const int wid = tid >> 5, lane = tid & 31;

    const int wq = (wid & 3)*32, nw = (wid >> 2)*64;
    const int l15 = lane & 15;
    const int lq = lane >> 4;
    const int g = lane >> 2, cq = (lane & 3)*2;

    float acc[2][8][4];
    #pragma unroll
    for (int mf = 0; mf < 2; mf++)
        #pragma unroll
        for (int nf = 0; nf < 8; nf++)
            #pragma unroll
            for (int e = 0; e < 4; e++) acc[mf][nf][e] = 0.f;

    for (int ks0 = 0; ks0 < 8; ++ks0) {
        const int k0 = ks0*64;
        __syncthreads();
        #pragma unroll
        for (int i = 0; i < 4; i++) {
            const int f = i*256 + tid;
            const int row = f >> 3, c8 = f & 7;
            cp16(smb + GQ_AH + row*144 + c8*16,
                 g_Xh + (size_t)(bm + row)*512 + k0 + c8*8);
        }
        #pragma unroll
        for (int i = 0; i < 4; i++) {
            const int f = i*256 + tid;
            const int row = f >> 4, c16 = f & 15;
            cp16(smb + GQ_BH + row*272 + c16*16,
                 g_Wqh + (size_t)(k0 + row)*(3*DMODEL) + bn + c16*8);
        }
        CP_COMMIT();
        CP_WAIT0();
        __syncthreads();

        #pragma unroll
        for (int ks = 0; ks < 4; ks++) {
            uint32_t ah[2][4];
            #pragma unroll
            for (int mf = 0; mf < 2; mf++)
                ldsm4(ah[mf], smb + GQ_AH + (wq + mf*16 + l15)*144 + (ks*16 + lq*8)*2);
            #pragma unroll
            for (int nf = 0; nf < 8; nf++) {
                uint32_t bhf[2];
                ldsm2t(bhf, smb + GQ_BH + (ks*16 + l15)*272 + (nw + nf*8)*2);
                #pragma unroll
                for (int mf = 0; mf < 2; mf++)
                    mma16816(acc[mf][nf], ah[mf], bhf);
            }
        }
    }

    const int which = bn >> 9;
    __half* dst = (which == 0) ? g_Qh : (which == 1) ? g_Kh : g_Vh;
    const int cbase = bn & 511;
    #pragma unroll
    for (int mf = 0; mf < 2; mf++) {
        const int r = bm + wq + mf*16 + g;
        const int bidx = r >> 11, nidx = r & (NSEQ-1);
        #pragma unroll
        for (int nf = 0; nf < 8; nf++) {
            const int cb = cbase + nw + nf*8 + cq;
            const int h = cb >> 6, dd = cb & 63;
            __half* hp = dst + (((size_t)bidx*HEADS + h)*NSEQ + nidx)*DH + dd;
            *(uint32_t*)(hp)        = pack2hi(acc[mf][nf][0], acc[mf][nf][1]);
            *(uint32_t*)(hp + 8*DH) = pack2hi(acc[mf][nf][2], acc[mf][nf][3]);
        }
    }
}

// ============ attn pass 1: rowsums + O; 64-key slabs, 2 CTAs/SM ============
#define AF_QH    0
#define AF_ST    18432
#define AF_BUFSZ 18432
#define AF_INV   55296
#define AF_PS    55808
#define AF_SMEM  56832

__global__ void __launch_bounds__(256, 2)
attn_pass1()
{
    extern __shared__ char sm[];
    const uint32_t smb = smem_u32(sm);
    const int tid = threadIdx.x;
    const int wid = tid >> 5, lane = tid & 31;
    const int q0 = blockIdx.x * 128;
    const int bh = blockIdx.y;

    const int mw = (wid & 3)*32, nw = (wid >> 2)*32;
    const int l15 = lane & 15, l7 = lane & 7;
    const int lh = (lane >> 3) & 1, lq = lane >> 4;
    const int g = lane >> 2, cq = (lane & 3)*2;

    const __half* Qb = g_Qh + ((size_t)bh*NSEQ + q0)*DH;
    const __half* Kb = g_Kh + (size_t)bh*NSEQ*DH;
    const __half* Vb = g_Vh + (size_t)bh*NSEQ*DH;

    // stage Q + slab 0 via cp.async (one group)
    #pragma unroll
    for (int i = 0; i < 4; i++) {
        const int f = i*256 + tid;
        const int row = f >> 3, c8 = f & 7;
        cp16(smb + AF_QH + row*144 + c8*16, Qb + (size_t)row*DH + c8*8);
    }
    #pragma unroll
    for (int i = 0; i < 2; i++) {
        const int f = i*256 + tid;
        const int row = f >> 3, c8 = f & 7;
        const int boff = row*144 + c8*16;
        cp16(smb + AF_ST + boff,        Kb + (size_t)row*DH + c8*8);
        cp16(smb + AF_ST + 9216 + boff, Vb + (size_t)row*DH + c8*8);
    }
    CP_COMMIT();

    float acc_o[2][8][4];
    #pragma unroll
    for (int mf = 0; mf < 2; mf++)
        #pragma unroll
        for (int nf = 0; nf < 8; nf++)
            #pragma unroll
            for (int e = 0; e < 4; e++) acc_o[mf][nf][e] = 0.f;
    float psum[2][2] = {{0.f, 0.f}, {0.f, 0.f}};

    float decv[4][2];
    #pragma unroll
    for (int nf = 0; nf < 4; nf++) {
        decv[nf][0] = __expf((float)(nw + nf*8 + cq)     * -0.02f);
        decv[nf][1] = __expf((float)(nw + nf*8 + cq + 1) * -0.02f);
    }

    for (int kt = 0; kt < 32; ++kt) {
        CP_WAIT0();
        __syncthreads();
        const uint32_t bK = smb + AF_ST + (kt & 1)*AF_BUFSZ;
        const uint32_t bV = bK + 9216;

        if (kt < 31) {
            const int kb1 = (kt + 1)*64;
            const uint32_t nK = smb + AF_ST + ((kt + 1) & 1)*AF_BUFSZ;
            #pragma unroll
            for (int i = 0; i < 2; i++) {
                const int f = i*256 + tid;
                const int row = f >> 3, c8 = f & 7;
                const int boff = row*144 + c8*16;
                cp16(nK + boff,        Kb + (size_t)(kb1 + row)*DH + c8*8);
                cp16(nK + 9216 + boff, Vb + (size_t)(kb1 + row)*DH + c8*8);
            }
            CP_COMMIT();
        }

        float acc_s[2][4][4];
        #pragma unroll
        for (int mf = 0; mf < 2; mf++)
            #pragma unroll
            for (int nf = 0; nf < 4; nf++)
                #pragma unroll
                for (int e = 0; e < 4; e++) acc_s[mf][nf][e] = 0.f;
        #pragma unroll
        for (int ks = 0; ks < 4; ks++) {
            uint32_t ah[2][4];
            #pragma unroll
            for (int mf = 0; mf < 2; mf++)
                ldsm4(ah[mf], smb + AF_QH + (mw + mf*16 + l15)*144 + (ks*16 + lq*8)*2);
            #pragma unroll
            for (int nf = 0; nf < 4; nf++) {
                uint32_t bhf[2];
                ldsm2(bhf, bK + (nw + nf*8 + l7)*144 + (ks*16 + lh*8)*2);
                #pragma unroll
                for (int mf = 0; mf < 2; mf++)
                    mma16816(acc_s[mf][nf], ah[mf], bhf);
            }
        }

        uint32_t eh[2][4][2];
        #pragma unroll
        for (int nf = 0; nf < 4; nf++) {
            const float dec0 = decv[nf][0], dec1 = decv[nf][1];
            decv[nf][0] = dec0 * DECSTEP64;
            decv[nf][1] = dec1 * DECSTEP64;
            #pragma unroll
            for (int mf = 0; mf < 2; mf++) {
                const float e0 = __expf(fmaf(acc_s[mf][nf][0], 0.125f, dec0));
                const float e1 = __expf(fmaf(acc_s[mf][nf][1], 0.125f, dec1));
                const float e2 = __expf(fmaf(acc_s[mf][nf][2], 0.125f, dec0));
                const float e3 = __expf(fmaf(acc_s[mf][nf][3], 0.125f, dec1));
                psum[mf][0] += e0 + e1;
                psum[mf][1] += e2 + e3;
                eh[mf][nf][0] = pack2hi(e0, e1);
                eh[mf][nf][1] = pack2hi(e2, e3);
            }
        }

        #pragma unroll
        for (int ks2 = 0; ks2 < 2; ks2++) {
            uint32_t pah[2][4];
            #pragma unroll
            for (int mf = 0; mf < 2; mf++) {
                pah[mf][0] = eh[mf][2*ks2][0];
                pah[mf][1] = eh[mf][2*ks2][1];
                pah[mf][2] = eh[mf][2*ks2+1][0];
                pah[mf][3] = eh[mf][2*ks2+1][1];
            }
            #pragma unroll
            for (int nf = 0; nf < 8; nf++) {
                uint32_t bhf[2];
                ldsm2t(bhf, bV + (nw + ks2*16 + l15)*144 + (nf*8)*2);
                #pragma unroll
                for (int mf = 0; mf < 2; mf++)
                    mma16816(acc_o[mf][nf], pah[mf], bhf);
            }
        }
    }

    #pragma unroll
    for (int off = 1; off < 4; off <<= 1) {
        psum[0][0] += __shfl_xor_sync(0xffffffffu, psum[0][0], off);
        psum[0][1] += __shfl_xor_sync(0xffffffffu, psum[0][1], off);
        psum[1][0] += __shfl_xor_sync(0xffffffffu, psum[1][0], off);
        psum[1][1] += __shfl_xor_sync(0xffffffffu, psum[1][1], off);
    }
    __syncthreads();
    float* ps   = (float*)(sm + AF_PS);
    float* invs = (float*)(sm + AF_INV);
    if ((lane & 3) == 0) {
        #pragma unroll
        for (int mf = 0; mf < 2; mf++)
            #pragma unroll
            for (int h = 0; h < 2; h++)
                ps[wid*32 + mf*16 + h*8 + g] = psum[mf][h];
    }
    __syncthreads();
    if (tid < 128) {
        const float v = 1.0f / (ps[tid] + ps[tid + 128]);
        invs[tid] = v;
        g_inv[(size_t)bh*NSEQ + q0 + tid] = v;
    }
    __syncthreads();

    #pragma unroll
    for (int mf = 0; mf < 2; mf++) {
        const float inv0 = invs[mw + mf*16 + g];
        const float inv1 = invs[mw + mf*16 + 8 + g];
        #pragma unroll
        for (int nf = 0; nf < 8; nf++) {
            acc_o[mf][nf][0] *= inv0; acc_o[mf][nf][1] *= inv0;
            acc_o[mf][nf][2] *= inv1; acc_o[mf][nf][3] *= inv1;
        }
    }
    float* exch = (float*)(sm + AF_ST);
    if (wid >= 4) {
        #pragma unroll
        for (int mf = 0; mf < 2; mf++)
            #pragma unroll
            for (int nf = 0; nf < 8; nf++) {
                float* e0 = exch + (wid & 3)*2048 + (mf*16 + g)*64 + nf*8 + cq;
                *(float2*)(e0)       = make_float2(acc_o[mf][nf][0], acc_o[mf][nf][1]);
                *(float2*)(e0 + 512) = make_float2(acc_o[mf][nf][2], acc_o[mf][nf][3]);
            }
    }
    __syncthreads();
    if (wid < 4) {
        const int b = bh >> 3, h = bh & 7;
        #pragma unroll
        for (int mf = 0; mf < 2; mf++) {
            const int r0 = q0 + mw + mf*16 + g;
            #pragma unroll
            for (int nf = 0; nf < 8; nf++) {
                const float* e0 = exch + wid*2048 + (mf*16 + g)*64 + nf*8 + cq;
                const float2 p0 = *(const float2*)(e0);
                const float2 p1 = *(const float2*)(e0 + 512);
                float* op = g_O + (size_t)(b*NSEQ + r0)*DMODEL + h*DH + nf*8 + cq;
                *(float2*)(op)            = make_float2(acc_o[mf][nf][0] + p0.x,
                                                        acc_o[mf][nf][1] + p0.y);
                *(float2*)(op + 8*DMODEL) = make_float2(acc_o[mf][nf][2] + p1.x,
                                                        acc_o[mf][nf][3] + p1.y);
            }
        }
    }
}

// ===== merged kernel: blocks 0..255 = unify GEMM (1-product); rest pass2 ===
#define PU_SMEM 55808

__global__ void __launch_bounds__(256, 2)
pass2_unify(float* __restrict__ attn, const float* __restrict__ B,
            const float* __restrict__ bias)
{
    extern __shared__ char sm[];
    const uint32_t smb = smem_u32(sm);
    const int tid = threadIdx.x;
    const int wid = tid >> 5, lane = tid & 31;
    const int l15 = lane & 15, l7 = lane & 7;
    const int lh = (lane >> 3) & 1, lq = lane >> 4;
    const int g = lane >> 2, cq = (lane & 3)*2;

    if (blockIdx.x < 256) {
        // ------------- unify GEMM role (A hi x B hi, 1-product) -----------
        const int bn = (blockIdx.x & 3)*128;
        const int bm = (blockIdx.x >> 2)*128;
        const int wq = (wid & 3)*32, nw = (wid >> 2)*64;

        float acc[2][8][4];
        #pragma unroll
        for (int mf = 0; mf < 2; mf++)
            #pragma unroll
            for (int nf = 0; nf < 8; nf++)
                #pragma unroll
                for (int e = 0; e < 4; e++) acc[mf][nf][e] = 0.f;

        for (int ks0 = 0; ks0 < 8; ++ks0) {
            const int k0 = ks0*64;
            __syncthreads();
            #pragma unroll
            for (int i = 0; i < 8; i++) {
                const int f = i*256 + tid;
                float4 a = *(const float4*)(g_O + (size_t)(bm + (f >> 4))*512 + k0 + (f & 15)*4);
                *(uint2*)(sm + (f >> 4)*144 + (f & 15)*8) = pack_hi4(a);
            }
            #pragma unroll
            for (int i = 0; i < 8; i++) {
                const int f = i*256 + tid;
                float4 b = *(const float4*)(B + (size_t)(k0 + (f >> 5))*DMODEL + bn + (f & 31)*4);
                *(uint2*)(sm + 18432 + (f >> 5)*272 + (f & 31)*8) = pack_hi4(b);
            }
            __syncthreads();

            #pragma unroll
            for (int ks = 0; ks < 4; ks++) {
                uint32_t ah[2][4];
                #pragma unroll
                for (int mf = 0; mf < 2; mf++)
                    ldsm4(ah[mf], smb + (wq + mf*16 + l15)*144 + (ks*16 + lq*8)*2);
                #pragma unroll
                for (int nf = 0; nf < 8; nf++) {
                    uint32_t bhf[2];
                    ldsm2t(bhf, smb + 18432 + (ks*16 + l15)*272 + (nw + nf*8)*2);
                    #pragma unroll
                    for (int mf = 0; mf < 2; mf++)
                        mma16816(acc[mf][nf], ah[mf], bhf);
                }
            }
        }

        #pragma unroll
        for (int mf = 0; mf < 2; mf++) {
            const int r = bm + wq + mf*16 + g;
            #pragma unroll
            for (int nf = 0; nf < 8; nf++) {
                const int col = bn + nw + nf*8 + cq;
                const float b0 = bias[col], b1 = bias[col + 1];
                float* yr = g_Y + (size_t)r*DMODEL + col;
                *(float2*)(yr)            = make_float2(acc[mf][nf][0] + b0,
                                                        acc[mf][nf][1] + b1);
                *(float2*)(yr + 8*DMODEL) = make_float2(acc[mf][nf][2] + b0,
                                                        acc[mf][nf][3] + b1);
            }
        }
    } else {
        // ---------------- attn pass-2 role (cp.async K staging) ----------
        const int t = blockIdx.x - 256;
        const int q0 = (t & 15)*128;
        const int bh = t >> 4;
        const int mw = (wid & 3)*32, nw = (wid >> 2)*64;
        float* invs = (float*)(sm + 55296);

        const __half* Qb = g_Qh + ((size_t)bh*NSEQ + q0)*DH;
        const __half* Kb = g_Kh + (size_t)bh*NSEQ*DH;

        #pragma unroll
        for (int i = 0; i < 4; i++) {
            const int f = i*256 + tid;
            const int row = f >> 3, c8 = f & 7;
            cp16(smb + row*144 + c8*16, Qb + (size_t)row*DH + c8*8);
        }
        #pragma unroll
        for (int i = 0; i < 4; i++) {
            const int f = i*256 + tid;
            const int row = f >> 3, c8 = f & 7;
            cp16(smb + 18432 + row*144 + c8*16, Kb + (size_t)row*DH + c8*8);
        }
        CP_COMMIT();
        if (tid < 128) invs[tid] = g_inv[(size_t)bh*NSEQ + q0 + tid];

        float decv[8][2];
        #pragma unroll
        for (int nf = 0; nf < 8; nf++) {
            decv[nf][0] = __expf((float)(nw + nf*8 + cq)     * -0.02f);
            decv[nf][1] = __expf((float)(nw + nf*8 + cq + 1) * -0.02f);
        }

        for (int kt = 0; kt < 16; ++kt) {
            CP_WAIT0();
            __syncthreads();
            const uint32_t bK = smb + 18432 + (kt & 1)*18432;

            if (kt < 15) {
                const int kb1 = (kt + 1)*128;
                const uint32_t nK = smb + 18432 + ((kt + 1) & 1)*18432;
                #pragma unroll
                for (int i = 0; i < 4; i++) {
                    const int f = i*256 + tid;
                    const int row = f >> 3, c8 = f & 7;
                    cp16(nK + row*144 + c8*16, Kb + (size_t)(kb1 + row)*DH + c8*8);
                }
                CP_COMMIT();
            }

            const int kb = kt*128;
            float acc_s[2][8][4];
            #pragma unroll
            for (int mf = 0; mf < 2; mf++)
                #pragma unroll
                for (int nf = 0; nf < 8; nf++)
                    #pragma unroll
                    for (int e = 0; e < 4; e++) acc_s[mf][nf][e] = 0.f;
            #pragma unroll
            for (int ks = 0; ks < 4; ks++) {
                uint32_t ah[2][4];
                #pragma unroll
                for (int mf = 0; mf < 2; mf++)
                    ldsm4(ah[mf], smb + (mw + mf*16 + l15)*144 + (ks*16 + lq*8)*2);
                #pragma unroll
                for (int nf = 0; nf < 8; nf++) {
                    uint32_t bhf[2];
                    ldsm2(bhf, bK + (nw + nf*8 + l7)*144 + (ks*16 + lh*8)*2);
                    #pragma unroll
                    for (int mf = 0; mf < 2; mf++)
                        mma16816(acc_s[mf][nf], ah[mf], bhf);
                }
            }

            #pragma unroll
            for (int nf = 0; nf < 8; nf++) {
                const float dec0 = decv[nf][0], dec1 = decv[nf][1];
                decv[nf][0] = dec0 * DECSTEP128;
                decv[nf][1] = dec1 * DECSTEP128;
                const int c = nw + nf*8 + cq;
                #pragma unroll
                for (int mf = 0; mf < 2; mf++) {
                    const float inv0 = invs[mw + mf*16 + g];
                    const float inv1 = invs[mw + mf*16 + 8 + g];
                    const int r0 = q0 + mw + mf*16 + g;
                    const float e0 = __expf(fmaf(acc_s[mf][nf][0], 0.125f, dec0)) * inv0;
                    const float e1 = __expf(fmaf(acc_s[mf][nf][1], 0.125f, dec1)) * inv0;
                    const float e2 = __expf(fmaf(acc_s[mf][nf][2], 0.125f, dec0)) * inv1;
                    const float e3 = __expf(fmaf(acc_s[mf][nf][3], 0.125f, dec1)) * inv1;
                    float* p = attn + ((size_t)bh*NSEQ + r0)*NSEQ + kb + c;
                    *(float2*)(p)          = make_float2(e0, e1);
                    *(float2*)(p + 8*NSEQ) = make_float2(e2, e3);
                }
            }
        }
    }
}

// ---------------- LayerNorm (unchanged; clock canary ~13 µs) ---------------
__global__ void __launch_bounds__(256)
ln_kernel(const float* __restrict__ gamma, const float* __restrict__ beta,
          float* __restrict__ out)
{
    const int r = blockIdx.x, tid = threadIdx.x;
    const float* y = g_Y + (size_t)r*DMODEL;
    const float a = y[tid], b = y[tid + 256];
    float s  = a + b;
    float sq = a*a + b*b;
    #pragma unroll
    for (int off = 16; off; off >>= 1) {
        s  += __shfl_xor_sync(0xffffffffu, s,  off);
        sq += __shfl_xor_sync(0xffffffffu, sq, off);
    }
    __shared__ float ws[8], wq[8];
    __shared__ float mean_s, inv_s;
    if ((tid & 31) == 0) { ws[tid >> 5] = s; wq[tid >> 5] = sq; }
    __syncthreads();
    if (tid == 0) {
        float S = 0.f, Q = 0.f;
        #pragma unroll
        for (int i = 0; i < 8; i++) { S += ws[i]; Q += wq[i]; }
        const float mean = S * (1.0f/512.0f);
        const float var  = Q * (1.0f/512.0f) - mean*mean;
        mean_s = mean;
        inv_s  = rsqrtf(var + 1e-5f);
    }
    __syncthreads();
    out[(size_t)r*DMODEL + tid]       = (a - mean_s)*inv_s*gamma[tid]       + beta[tid];
    out[(size_t)r*DMODEL + tid + 256] = (b - mean_s)*inv_s*gamma[tid + 256] + beta[tid + 256];
}

// ---------------- launch ---------------------------------------------------
extern "C" void kernel_launch(void* const* d_in, const int* in_sizes, int n_in,
                              void* d_out, int out_size)
{
    const float* x        = (const float*)d_in[0];
    const float* w_qkv    = (const float*)d_in[1];
    const float* w_unify  = (const float*)d_in[2];
    const float* b_unify  = (const float*)d_in[3];
    const float* ln_gamma = (const float*)d_in[4];
    const float* ln_beta  = (const float*)d_in[5];

    float* out_ln   = (float*)d_out;
    float* out_attn = out_ln + (size_t)ROWS*DMODEL;

    cudaFuncSetAttribute(gemm_qkv,    cudaFuncAttributeMaxDynamicSharedMemorySize, GQ_SMEM);
    cudaFuncSetAttribute(attn_pass1,  cudaFuncAttributeMaxDynamicSharedMemorySize, AF_SMEM);
    cudaFuncSetAttribute(pass2_unify, cudaFuncAttributeMaxDynamicSharedMemorySize, PU_SMEM);

    // 0) one-time fp16 conversion of x and w_qkv
    cvt16<<<(unsigned)((X4 + W4 + 255)/256), 256>>>(x, w_qkv);
    // 1) QKV projection -> fp16 [bh][n][dh]
    gemm_qkv<<<dim3(12, 64), 256, GQ_SMEM>>>();
    // 2) attention pass 1: rowsums (g_inv) + O (g_O), 2 CTAs/SM
    attn_pass1<<<dim3(16, 32), 256, AF_SMEM>>>();
    // 3) merged: unify GEMM (blocks 0-255, 1-product) + attn pass 2
    pass2_unify<<<768, 256, PU_SMEM>>>(out_attn, w_unify, b_unify);
    // 4) LayerNorm -> first output
    ln_kernel<<<ROWS, 256>>>(ln_gamma, ln_beta, out_ln);
}

// round 17
// speedup vs baseline: 1.1436x; 1.0920x over previous
#include <cuda_runtime.h>
#include <cuda_fp16.h>
#include <cstdint>
#include <math.h>

#define HEADS   8
#define DH      64
#define NSEQ    2048
#define BATCH   4
#define DMODEL  512
#define ROWS    (BATCH*NSEQ)    // 8192
#define BHN     (BATCH*HEADS)   // 32

// ---------------- scratch (device globals; no allocations) ----------------
__device__ __half g_Xh[(size_t)ROWS*DMODEL];
__device__ __half g_Wqh[(size_t)DMODEL*3*DMODEL];
__device__ __half g_Qh[(size_t)BHN*NSEQ*DH];
__device__ __half g_Kh[(size_t)BHN*NSEQ*DH];
__device__ __half g_Vh[(size_t)BHN*NSEQ*DH];
__device__ float  g_O[(size_t)ROWS*DMODEL];
__device__ float  g_Y[(size_t)ROWS*DMODEL];
__device__ float  g_inv[(size_t)BHN*NSEQ];

#define DECSTEP128 0.0773047404f    // exp(-128/50)
#define DECSTEP64  0.2780373005f    // exp(-64/50)
#define LOG2E      1.4426950408889634f
#define SCALE_L2   0.1803368801111204f   // 0.125 * log2(e)

// ================= warp-level tensor core helpers (sm_80+ ISA) =============
__device__ __forceinline__ uint32_t smem_u32(const void* p) {
    uint32_t a;
    asm("{ .reg .u64 t; cvta.to.shared.u64 t, %1; cvt.u32.u64 %0, t; }"
        : "=r"(a) : "l"(p));
    return a;
}
__device__ __forceinline__ void ldsm4(uint32_t* r, uint32_t a) {
    asm volatile("ldmatrix.sync.aligned.m8n8.x4.shared.b16 {%0,%1,%2,%3}, [%4];"
        : "=r"(r[0]), "=r"(r[1]), "=r"(r[2]), "=r"(r[3]) : "r"(a));
}
__device__ __forceinline__ void ldsm2(uint32_t* r, uint32_t a) {
    asm volatile("ldmatrix.sync.aligned.m8n8.x2.shared.b16 {%0,%1}, [%2];"
        : "=r"(r[0]), "=r"(r[1]) : "r"(a));
}
__device__ __forceinline__ void ldsm2t(uint32_t* r, uint32_t a) {
    asm volatile("ldmatrix.sync.aligned.m8n8.x2.trans.shared.b16 {%0,%1}, [%2];"
        : "=r"(r[0]), "=r"(r[1]) : "r"(a));
}
__device__ __forceinline__ void mma16816(float* d, const uint32_t* a, const uint32_t* b) {
    asm volatile("mma.sync.aligned.m16n8k16.row.col.f32.f16.f16.f32 "
        "{%0,%1,%2,%3}, {%4,%5,%6,%7}, {%8,%9}, {%0,%1,%2,%3};"
        : "+f"(d[0]), "+f"(d[1]), "+f"(d[2]), "+f"(d[3])
        : "r"(a[0]), "r"(a[1]), "r"(a[2]), "r"(a[3]), "r"(b[0]), "r"(b[1]));
}
__device__ __forceinline__ void cp16(uint32_t dst, const void* src) {
    asm volatile("cp.async.cg.shared.global [%0], [%1], 16;" :: "r"(dst), "l"(src));
}
#define CP_COMMIT() asm volatile("cp.async.commit_group;" ::: "memory")
#define CP_WAIT0()  asm volatile("cp.async.wait_group 0;" ::: "memory")

// raw MUFU ex2 (same unit __expf uses; argument pre-scaled to log2 domain)
__device__ __forceinline__ float ex2f(float x) {
    float r;
    asm("ex2.approx.ftz.f32 %0, %1;" : "=f"(r) : "f"(x));
    return r;
}

__device__ __forceinline__ uint2 pack_hi4(float4 f) {
    uint2 u;
    asm("cvt.rn.f16x2.f32 %0, %1, %2;" : "=r"(u.x) : "f"(f.y), "f"(f.x));
    asm("cvt.rn.f16x2.f32 %0, %1, %2;" : "=r"(u.y) : "f"(f.w), "f"(f.z));
    return u;
}
__device__ __forceinline__ uint32_t pack2hi(float x, float y) {
    uint32_t r;
    asm("cvt.rn.f16x2.f32 %0, %1, %2;" : "=r"(r) : "f"(y), "f"(x));
    return r;
}

// ============ one-time fp32 -> fp16 conversion of x and w_qkv ==============
#define X4 ((size_t)ROWS*DMODEL/4)
#define W4 ((size_t)DMODEL*3*DMODEL/4)

__global__ void __launch_bounds__(256)
cvt16(const float* __restrict__ x, const float* __restrict__ w)
{
    const size_t i4 = (size_t)blockIdx.x*256 + threadIdx.x;
    if (i4 < X4) {
        ((uint2*)g_Xh)[i4] = pack_hi4(((const float4*)x)[i4]);
    } else if (i4 < X4 + W4) {
        const size_t j = i4 - X4;
        ((uint2*)g_Wqh)[j] = pack_hi4(((const float4*)w)[j]);
    }
}

// ======== QKV projection: 1-product fp16, cp.async staging =================
#define GQ_AH   0
#define GQ_BH   18432
#define GQ_SMEM 35840

__global__ void __launch_bounds__(256, 2)
gemm_qkv()
{
    extern __shared__ char sm[];
    const uint32_t smb = smem_u32(sm);

    const int bm = blockIdx.y * 128;
    const int bn = blockIdx.x * 128;
    const int tid = threadIdx.x;
    const int wid = tid >> 5, lane = tid & 31;

    const int wq = (wid & 3)*32, nw = (wid >> 2)*64;
    const int l15 = lane & 15;
    const int lq = lane >> 4;
    const int g = lane >> 2, cq = (lane & 3)*2;

    float acc[2][8][4];
    #pragma unroll
    for (int mf = 0; mf < 2; mf++)
        #pragma unroll
        for (int nf = 0; nf < 8; nf++)
            #pragma unroll
            for (int e = 0; e < 4; e++) acc[mf][nf][e] = 0.f;

    for (int ks0 = 0; ks0 < 8; ++ks0) {
        const int k0 = ks0*64;
        __syncthreads();
        #pragma unroll
        for (int i = 0; i < 4; i++) {
            const int f = i*256 + tid;
            const int row = f >> 3, c8 = f & 7;
            cp16(smb + GQ_AH + row*144 + c8*16,
                 g_Xh + (size_t)(bm + row)*512 + k0 + c8*8);
        }
        #pragma unroll
        for (int i = 0; i < 4; i++) {
            const int f = i*256 + tid;
            const int row = f >> 4, c16 = f & 15;
            cp16(smb + GQ_BH + row*272 + c16*16,
                 g_Wqh + (size_t)(k0 + row)*(3*DMODEL) + bn + c16*8);
        }
        CP_COMMIT();
        CP_WAIT0();
        __syncthreads();

        #pragma unroll
        for (int ks = 0; ks < 4; ks++) {
            uint32_t ah[2][4];
            #pragma unroll
            for (int mf = 0; mf < 2; mf++)
                ldsm4(ah[mf], smb + GQ_AH + (wq + mf*16 + l15)*144 + (ks*16 + lq*8)*2);
            #pragma unroll
            for (int nf = 0; nf < 8; nf++) {
                uint32_t bhf[2];
                ldsm2t(bhf, smb + GQ_BH + (ks*16 + l15)*272 + (nw + nf*8)*2);
                #pragma unroll
                for (int mf = 0; mf < 2; mf++)
                    mma16816(acc[mf][nf], ah[mf], bhf);
            }
        }
    }

    const int which = bn >> 9;
    __half* dst = (which == 0) ? g_Qh : (which == 1) ? g_Kh : g_Vh;
    const int cbase = bn & 511;
    #pragma unroll
    for (int mf = 0; mf < 2; mf++) {
        const int r = bm + wq + mf*16 + g;
        const int bidx = r >> 11, nidx = r & (NSEQ-1);
        #pragma unroll
        for (int nf = 0; nf < 8; nf++) {
            const int cb = cbase + nw + nf*8 + cq;
            const int h = cb >> 6, dd = cb & 63;
            __half* hp = dst + (((size_t)bidx*HEADS + h)*NSEQ + nidx)*DH + dd;
            *(uint32_t*)(hp)        = pack2hi(acc[mf][nf][0], acc[mf][nf][1]);
            *(uint32_t*)(hp + 8*DH) = pack2hi(acc[mf][nf][2], acc[mf][nf][3]);
        }
    }
}

// ============ attn pass 1: rowsums + O; 64-key slabs, 2 CTAs/SM ============
#define AF_QH    0
#define AF_ST    18432
#define AF_BUFSZ 18432
#define AF_INV   55296
#define AF_PS    55808
#define AF_SMEM  56832

__global__ void __launch_bounds__(256, 2)
attn_pass1()
{
    extern __shared__ char sm[];
    const uint32_t smb = smem_u32(sm);
    const int tid = threadIdx.x;
    const int wid = tid >> 5, lane = tid & 31;
    const int q0 = blockIdx.x * 128;
    const int bh = blockIdx.y;

    const int mw = (wid & 3)*32, nw = (wid >> 2)*32;
    const int l15 = lane & 15, l7 = lane & 7;
    const int lh = (lane >> 3) & 1, lq = lane >> 4;
    const int g = lane >> 2, cq = (lane & 3)*2;

    const __half* Qb = g_Qh + ((size_t)bh*NSEQ + q0)*DH;
    const __half* Kb = g_Kh + (size_t)bh*NSEQ*DH;
    const __half* Vb = g_Vh + (size_t)bh*NSEQ*DH;

    #pragma unroll
    for (int i = 0; i < 4; i++) {
        const int f = i*256 + tid;
        const int row = f >> 3, c8 = f & 7;
        cp16(smb + AF_QH + row*144 + c8*16, Qb + (size_t)row*DH + c8*8);
    }
    #pragma unroll
    for (int i = 0; i < 2; i++) {
        const int f = i*256 + tid;
        const int row = f >> 3, c8 = f & 7;
        const int boff = row*144 + c8*16;
        cp16(smb + AF_ST + boff,        Kb + (size_t)row*DH + c8*8);
        cp16(smb + AF_ST + 9216 + boff, Vb + (size_t)row*DH + c8*8);
    }
    CP_COMMIT();

    float acc_o[2][8][4];
    #pragma unroll
    for (int mf = 0; mf < 2; mf++)
        #pragma unroll
        for (int nf = 0; nf < 8; nf++)
            #pragma unroll
            for (int e = 0; e < 4; e++) acc_o[mf][nf][e] = 0.f;
    float psum[2][2] = {{0.f, 0.f}, {0.f, 0.f}};

    // decay bias tracked in log2 domain: decl2 = log2e * exp(-k/50)
    float decv[4][2];
    #pragma unroll
    for (int nf = 0; nf < 4; nf++) {
        decv[nf][0] = LOG2E * __expf((float)(nw + nf*8 + cq)     * -0.02f);
        decv[nf][1] = LOG2E * __expf((float)(nw + nf*8 + cq + 1) * -0.02f);
    }

    for (int kt = 0; kt < 32; ++kt) {
        CP_WAIT0();
        __syncthreads();
        const uint32_t bK = smb + AF_ST + (kt & 1)*AF_BUFSZ;
        const uint32_t bV = bK + 9216;

        if (kt < 31) {
            const int kb1 = (kt + 1)*64;
            const uint32_t nK = smb + AF_ST + ((kt + 1) & 1)*AF_BUFSZ;
            #pragma unroll
            for (int i = 0; i < 2; i++) {
                const int f = i*256 + tid;
                const int row = f >> 3, c8 = f & 7;
                const int boff = row*144 + c8*16;
                cp16(nK + boff,        Kb + (size_t)(kb1 + row)*DH + c8*8);
                cp16(nK + 9216 + boff, Vb + (size_t)(kb1 + row)*DH + c8*8);
            }
            CP_COMMIT();
        }

        float acc_s[2][4][4];
        #pragma unroll
        for (int mf = 0; mf < 2; mf++)
            #pragma unroll
            for (int nf = 0; nf < 4; nf++)
                #pragma unroll
                for (int e = 0; e < 4; e++) acc_s[mf][nf][e] = 0.f;
        #pragma unroll
        for (int ks = 0; ks < 4; ks++) {
            uint32_t ah[2][4];
            #pragma unroll
            for (int mf = 0; mf < 2; mf++)
                ldsm4(ah[mf], smb + AF_QH + (mw + mf*16 + l15)*144 + (ks*16 + lq*8)*2);
            #pragma unroll
            for (int nf = 0; nf < 4; nf++) {
                uint32_t bhf[2];
                ldsm2(bhf, bK + (nw + nf*8 + l7)*144 + (ks*16 + lh*8)*2);
                #pragma unroll
                for (int mf = 0; mf < 2; mf++)
                    mma16816(acc_s[mf][nf], ah[mf], bhf);
            }
        }

        uint32_t eh[2][4][2];
        #pragma unroll
        for (int nf = 0; nf < 4; nf++) {
            const float dec0 = decv[nf][0], dec1 = decv[nf][1];
            decv[nf][0] = dec0 * DECSTEP64;
            decv[nf][1] = dec1 * DECSTEP64;
            #pragma unroll
            for (int mf = 0; mf < 2; mf++) {
                const float e0 = ex2f(fmaf(acc_s[mf][nf][0], SCALE_L2, dec0));
                const float e1 = ex2f(fmaf(acc_s[mf][nf][1], SCALE_L2, dec1));
                const float e2 = ex2f(fmaf(acc_s[mf][nf][2], SCALE_L2, dec0));
                const float e3 = ex2f(fmaf(acc_s[mf][nf][3], SCALE_L2, dec1));
                psum[mf][0] += e0 + e1;
                psum[mf][1] += e2 + e3;
                eh[mf][nf][0] = pack2hi(e0, e1);
                eh[mf][nf][1] = pack2hi(e2, e3);
            }
        }

        #pragma unroll
        for (int ks2 = 0; ks2 < 2; ks2++) {
            uint32_t pah[2][4];
            #pragma unroll
            for (int mf = 0; mf < 2; mf++) {
                pah[mf][0] = eh[mf][2*ks2][0];
                pah[mf][1] = eh[mf][2*ks2][1];
                pah[mf][2] = eh[mf][2*ks2+1][0];
                pah[mf][3] = eh[mf][2*ks2+1][1];
            }
            #pragma unroll
            for (int nf = 0; nf < 8; nf++) {
                uint32_t bhf[2];
                ldsm2t(bhf, bV + (nw + ks2*16 + l15)*144 + (nf*8)*2);
                #pragma unroll
                for (int mf = 0; mf < 2; mf++)
                    mma16816(acc_o[mf][nf], pah[mf], bhf);
            }
        }
    }

    #pragma unroll
    for (int off = 1; off < 4; off <<= 1) {
        psum[0][0] += __shfl_xor_sync(0xffffffffu, psum[0][0], off);
        psum[0][1] += __shfl_xor_sync(0xffffffffu, psum[0][1], off);
        psum[1][0] += __shfl_xor_sync(0xffffffffu, psum[1][0], off);
        psum[1][1] += __shfl_xor_sync(0xffffffffu, psum[1][1], off);
    }
    __syncthreads();
    float* ps   = (float*)(sm + AF_PS);
    float* invs = (float*)(sm + AF_INV);
    if ((lane & 3) == 0) {
        #pragma unroll
        for (int mf = 0; mf < 2; mf++)
            #pragma unroll
            for (int h = 0; h < 2; h++)
                ps[wid*32 + mf*16 + h*8 + g] = psum[mf][h];
    }
    __syncthreads();
    if (tid < 128) {
        const float v = 1.0f / (ps[tid] + ps[tid + 128]);
        invs[tid] = v;
        g_inv[(size_t)bh*NSEQ + q0 + tid] = v;
    }
    __syncthreads();

    #pragma unroll
    for (int mf = 0; mf < 2; mf++) {
        const float inv0 = invs[mw + mf*16 + g];
        const float inv1 = invs[mw + mf*16 + 8 + g];
        #pragma unroll
        for (int nf = 0; nf < 8; nf++) {
            acc_o[mf][nf][0] *= inv0; acc_o[mf][nf][1] *= inv0;
            acc_o[mf][nf][2] *= inv1; acc_o[mf][nf][3] *= inv1;
        }
    }
    float* exch = (float*)(sm + AF_ST);
    if (wid >= 4) {
        #pragma unroll
        for (int mf = 0; mf < 2; mf++)
            #pragma unroll
            for (int nf = 0; nf < 8; nf++) {
                float* e0 = exch + (wid & 3)*2048 + (mf*16 + g)*64 + nf*8 + cq;
                *(float2*)(e0)       = make_float2(acc_o[mf][nf][0], acc_o[mf][nf][1]);
                *(float2*)(e0 + 512) = make_float2(acc_o[mf][nf][2], acc_o[mf][nf][3]);
            }
    }
    __syncthreads();
    if (wid < 4) {
        const int b = bh >> 3, h = bh & 7;
        #pragma unroll
        for (int mf = 0; mf < 2; mf++) {
            const int r0 = q0 + mw + mf*16 + g;
            #pragma unroll
            for (int nf = 0; nf < 8; nf++) {
                const float* e0 = exch + wid*2048 + (mf*16 + g)*64 + nf*8 + cq;
                const float2 p0 = *(const float2*)(e0);
                const float2 p1 = *(const float2*)(e0 + 512);
                float* op = g_O + (size_t)(b*NSEQ + r0)*DMODEL + h*DH + nf*8 + cq;
                *(float2*)(op)            = make_float2(acc_o[mf][nf][0] + p0.x,
                                                        acc_o[mf][nf][1] + p0.y);
                *(float2*)(op + 8*DMODEL) = make_float2(acc_o[mf][nf][2] + p1.x,
                                                        acc_o[mf][nf][3] + p1.y);
            }
        }
    }
}

// ===== merged kernel: blocks 0..255 = unify GEMM (1-product); rest pass2 ===
#define PU_SMEM 55808

__global__ void __launch_bounds__(256, 2)
pass2_unify(float* __restrict__ attn, const float* __restrict__ B,
            const float* __restrict__ bias)
{
    extern __shared__ char sm[];
    const uint32_t smb = smem_u32(sm);
    const int tid = threadIdx.x;
    const int wid = tid >> 5, lane = tid & 31;
    const int l15 = lane & 15, l7 = lane & 7;
    const int lh = (lane >> 3) & 1, lq = lane >> 4;
    const int g = lane >> 2, cq = (lane & 3)*2;

    if (blockIdx.x < 256) {
        // ------------- unify GEMM role (A hi x B hi, 1-product) -----------
        const int bn = (blockIdx.x & 3)*128;
        const int bm = (blockIdx.x >> 2)*128;
        const int wq = (wid & 3)*32, nw = (wid >> 2)*64;

        float acc[2][8][4];
        #pragma unroll
        for (int mf = 0; mf < 2; mf++)
            #pragma unroll
            for (int nf = 0; nf < 8; nf++)
                #pragma unroll
                for (int e = 0; e < 4; e++) acc[mf][nf][e] = 0.f;

        for (int ks0 = 0; ks0 < 8; ++ks0) {
            const int k0 = ks0*64;
            __syncthreads();
            #pragma unroll
            for (int i = 0; i < 8; i++) {
                const int f = i*256 + tid;
                float4 a = *(const float4*)(g_O + (size_t)(bm + (f >> 4))*512 + k0 + (f & 15)*4);
                *(uint2*)(sm + (f >> 4)*144 + (f & 15)*8) = pack_hi4(a);
            }
            #pragma unroll
            for (int i = 0; i < 8; i++) {
                const int f = i*256 + tid;
                float4 b = *(const float4*)(B + (size_t)(k0 + (f >> 5))*DMODEL + bn + (f & 31)*4);
                *(uint2*)(sm + 18432 + (f >> 5)*272 + (f & 31)*8) = pack_hi4(b);
            }
            __syncthreads();

            #pragma unroll
            for (int ks = 0; ks < 4; ks++) {
                uint32_t ah[2][4];
                #pragma unroll
                for (int mf = 0; mf < 2; mf++)
                    ldsm4(ah[mf], smb + (wq + mf*16 + l15)*144 + (ks*16 + lq*8)*2);
                #pragma unroll
                for (int nf = 0; nf < 8; nf++) {
                    uint32_t bhf[2];
                    ldsm2t(bhf, smb + 18432 + (ks*16 + l15)*272 + (nw + nf*8)*2);
                    #pragma unroll
                    for (int mf = 0; mf < 2; mf++)
                        mma16816(acc[mf][nf], ah[mf], bhf);
                }
            }
        }

        #pragma unroll
        for (int mf = 0; mf < 2; mf++) {
            const int r = bm + wq + mf*16 + g;
            #pragma unroll
            for (int nf = 0; nf < 8; nf++) {
                const int col = bn + nw + nf*8 + cq;
                const float b0 = bias[col], b1 = bias[col + 1];
                float* yr = g_Y + (size_t)r*DMODEL + col;
                *(float2*)(yr)            = make_float2(acc[mf][nf][0] + b0,
                                                        acc[mf][nf][1] + b1);
                *(float2*)(yr + 8*DMODEL) = make_float2(acc[mf][nf][2] + b0,
                                                        acc[mf][nf][3] + b1);
            }
        }
    } else {
        // ---------------- attn pass-2 role (cp.async K staging) ----------
        const int t = blockIdx.x - 256;
        const int q0 = (t & 15)*128;
        const int bh = t >> 4;
        const int mw = (wid & 3)*32, nw = (wid >> 2)*64;
        float* invs = (float*)(sm + 55296);

        const __half* Qb = g_Qh + ((size_t)bh*NSEQ + q0)*DH;
        const __half* Kb = g_Kh + (size_t)bh*NSEQ*DH;

        #pragma unroll
        for (int i = 0; i < 4; i++) {
            const int f = i*256 + tid;
            const int row = f >> 3, c8 = f & 7;
            cp16(smb + row*144 + c8*16, Qb + (size_t)row*DH + c8*8);
        }
        #pragma unroll
        for (int i = 0; i < 4; i++) {
            const int f = i*256 + tid;
            const int row = f >> 3, c8 = f & 7;
            cp16(smb + 18432 + row*144 + c8*16, Kb + (size_t)row*DH + c8*8);
        }
        CP_COMMIT();
        if (tid < 128) invs[tid] = g_inv[(size_t)bh*NSEQ + q0 + tid];

        float decv[8][2];
        #pragma unroll
        for (int nf = 0; nf < 8; nf++) {
            decv[nf][0] = LOG2E * __expf((float)(nw + nf*8 + cq)     * -0.02f);
            decv[nf][1] = LOG2E * __expf((float)(nw + nf*8 + cq + 1) * -0.02f);
        }

        for (int kt = 0; kt < 16; ++kt) {
            CP_WAIT0();
            __syncthreads();
            const uint32_t bK = smb + 18432 + (kt & 1)*18432;

            if (kt < 15) {
                const int kb1 = (kt + 1)*128;
                const uint32_t nK = smb + 18432 + ((kt + 1) & 1)*18432;
                #pragma unroll
                for (int i = 0; i < 4; i++) {
                    const int f = i*256 + tid;
                    const int row = f >> 3, c8 = f & 7;
                    cp16(nK + row*144 + c8*16, Kb + (size_t)(kb1 + row)*DH + c8*8);
                }
                CP_COMMIT();
            }

            const int kb = kt*128;
            float acc_s[2][8][4];
            #pragma unroll
            for (int mf = 0; mf < 2; mf++)
                #pragma unroll
                for (int nf = 0; nf < 8; nf++)
                    #pragma unroll
                    for (int e = 0; e < 4; e++) acc_s[mf][nf][e] = 0.f;
            #pragma unroll
            for (int ks = 0; ks < 4; ks++) {
                uint32_t ah[2][4];
                #pragma unroll
                for (int mf = 0; mf < 2; mf++)
                    ldsm4(ah[mf], smb + (mw + mf*16 + l15)*144 + (ks*16 + lq*8)*2);
                #pragma unroll
                for (int nf = 0; nf < 8; nf++) {
                    uint32_t bhf[2];
                    ldsm2(bhf, bK + (nw + nf*8 + l7)*144 + (ks*16 + lh*8)*2);
                    #pragma unroll
                    for (int mf = 0; mf < 2; mf++)
                        mma16816(acc_s[mf][nf], ah[mf], bhf);
                }
            }

            #pragma unroll
            for (int nf = 0; nf < 8; nf++) {
                const float dec0 = decv[nf][0], dec1 = decv[nf][1];
                decv[nf][0] = dec0 * DECSTEP128;
                decv[nf][1] = dec1 * DECSTEP128;
                const int c = nw + nf*8 + cq;
                #pragma unroll
                for (int mf = 0; mf < 2; mf++) {
                    const float inv0 = invs[mw + mf*16 + g];
                    const float inv1 = invs[mw + mf*16 + 8 + g];
                    const int r0 = q0 + mw + mf*16 + g;
                    const float e0 = ex2f(fmaf(acc_s[mf][nf][0], SCALE_L2, dec0)) * inv0;
                    const float e1 = ex2f(fmaf(acc_s[mf][nf][1], SCALE_L2, dec1)) * inv0;
                    const float e2 = ex2f(fmaf(acc_s[mf][nf][2], SCALE_L2, dec0)) * inv1;
                    const float e3 = ex2f(fmaf(acc_s[mf][nf][3], SCALE_L2, dec1)) * inv1;
                    float* p = attn + ((size_t)bh*NSEQ + r0)*NSEQ + kb + c;
                    *(float2*)(p)          = make_float2(e0, e1);
                    *(float2*)(p + 8*NSEQ) = make_float2(e2, e3);
                }
            }
        }
    }
}

// ---------------- LayerNorm (unchanged; clock canary ~13 µs) ---------------
__global__ void __launch_bounds__(256)
ln_kernel(const float* __restrict__ gamma, const float* __restrict__ beta,
          float* __restrict__ out)
{
    const int r = blockIdx.x, tid = threadIdx.x;
    const float* y = g_Y + (size_t)r*DMODEL;
    const float a = y[tid], b = y[tid + 256];
    float s  = a + b;
    float sq = a*a + b*b;
    #pragma unroll
    for (int off = 16; off; off >>= 1) {
        s  += __shfl_xor_sync(0xffffffffu, s,  off);
        sq += __shfl_xor_sync(0xffffffffu, sq, off);
    }
    __shared__ float ws[8], wq[8];
    __shared__ float mean_s, inv_s;
    if ((tid & 31) == 0) { ws[tid >> 5] = s; wq[tid >> 5] = sq; }
    __syncthreads();
    if (tid == 0) {
        float S = 0.f, Q = 0.f;
        #pragma unroll
        for (int i = 0; i < 8; i++) { S += ws[i]; Q += wq[i]; }
        const float mean = S * (1.0f/512.0f);
        const float var  = Q * (1.0f/512.0f) - mean*mean;
        mean_s = mean;
        inv_s  = rsqrtf(var + 1e-5f);
    }
    __syncthreads();
    out[(size_t)r*DMODEL + tid]       = (a - mean_s)*inv_s*gamma[tid]       + beta[tid];
    out[(size_t)r*DMODEL + tid + 256] = (b - mean_s)*inv_s*gamma[tid + 256] + beta[tid + 256];
}

// ---------------- launch ---------------------------------------------------
extern "C" void kernel_launch(void* const* d_in, const int* in_sizes, int n_in,
                              void* d_out, int out_size)
{
    const float* x        = (const float*)d_in[0];
    const float* w_qkv    = (const float*)d_in[1];
    const float* w_unify  = (const float*)d_in[2];
    const float* b_unify  = (const float*)d_in[3];
    const float* ln_gamma = (const float*)d_in[4];
    const float* ln_beta  = (const float*)d_in[5];

    float* out_ln   = (float*)d_out;
    float* out_attn = out_ln + (size_t)ROWS*DMODEL;

    cudaFuncSetAttribute(gemm_qkv,    cudaFuncAttributeMaxDynamicSharedMemorySize, GQ_SMEM);
    cudaFuncSetAttribute(attn_pass1,  cudaFuncAttributeMaxDynamicSharedMemorySize, AF_SMEM);
    cudaFuncSetAttribute(pass2_unify, cudaFuncAttributeMaxDynamicSharedMemorySize, PU_SMEM);

    // 0) one-time fp16 conversion of x and w_qkv
    cvt16<<<(unsigned)((X4 + W4 + 255)/256), 256>>>(x, w_qkv);
    // 1) QKV projection -> fp16 [bh][n][dh]
    gemm_qkv<<<dim3(12, 64), 256, GQ_SMEM>>>();
    // 2) attention pass 1: rowsums (g_inv) + O (g_O), 2 CTAs/SM
    attn_pass1<<<dim3(16, 32), 256, AF_SMEM>>>();
    // 3) merged: unify GEMM (blocks 0-255, 1-product) + attn pass 2
    pass2_unify<<<768, 256, PU_SMEM>>>(out_attn, w_unify, b_unify);
    // 4) LayerNorm -> first output
    ln_kernel<<<ROWS, 256>>>(ln_gamma, ln_beta, out_ln);
}